// round 10
// baseline (speedup 1.0000x reference)
#include <cuda_runtime.h>

// DWT1DForward (db4, periodic, J=3) — register cascade, 8 floats/thread.
// Thread t owns x[8t..8t+7] -> lo1/hi1[4t..4t+3] -> lo2/hi2[2t..2t+1] -> x0/hi3[t].
// Halos: shfl everywhere; warp-edge lanes use smem edge slots / flat lo2 buffer.
// d_out floats: [x0: 1024x8192][hi1: 1024x32768][hi2: 1024x16384][hi3: 1024x8192]

#define N0      65536
#define NROWS   1024
#define S       2048
#define CHUNKS  (N0 / S)          // 32
#define THREADS 256

#define OFF_HI1 8388608u
#define OFF_HI2 41943040u
#define OFF_HI3 58720256u

// db4 decomposition filters, REVERSED (as the reference passes them in).
#define H0_0 ( 0.23037781330885523f)
#define H0_1 ( 0.7148465705525415f)
#define H0_2 ( 0.6308807679295904f)
#define H0_3 (-0.02798376941698385f)
#define H0_4 (-0.18703481171888114f)
#define H0_5 ( 0.030841381835986965f)
#define H0_6 ( 0.032883011666982945f)
#define H0_7 (-0.010597401784997278f)

#define H1_0 (-0.010597401784997278f)
#define H1_1 (-0.032883011666982945f)
#define H1_2 ( 0.030841381835986965f)
#define H1_3 ( 0.18703481171888114f)
#define H1_4 (-0.02798376941698385f)
#define H1_5 (-0.6308807679295904f)
#define H1_6 ( 0.7148465705525415f)
#define H1_7 (-0.23037781330885523f)

// out[m] = sum_{i=0..7} H_i * x[2m-3+i]
__device__ __forceinline__ float conv_lo(const float* p) {
    return fmaf(p[0], H0_0, fmaf(p[1], H0_1, fmaf(p[2], H0_2, fmaf(p[3], H0_3,
           fmaf(p[4], H0_4, fmaf(p[5], H0_5, fmaf(p[6], H0_6, p[7] * H0_7)))))));
}
__device__ __forceinline__ float conv_hi(const float* p) {
    return fmaf(p[0], H1_0, fmaf(p[1], H1_1, fmaf(p[2], H1_2, fmaf(p[3], H1_3,
           fmaf(p[4], H1_4, fmaf(p[5], H1_5, fmaf(p[6], H1_6, p[7] * H1_7)))))));
}

__global__ __launch_bounds__(THREADS)
void dwt3_reg8_kernel(const float* __restrict__ x, float* __restrict__ out)
{
    // Warp-edge fallback storage.
    __shared__ __align__(16) float4 eh1[THREADS + 2];  // eh1[t+1] = lo1[4t+1..4t+3]
    __shared__ __align__(16) float4 el1[THREADS + 2];  // el1[t+1] = lo1[4t..4t+2]
    __shared__ __align__(16) float  lo2s[524];         // lo2s[4+j] = lo2[j], j in [-3, 515)

    const int cta   = blockIdx.x;
    const int row   = cta >> 5;              // / CHUNKS
    const int chunk = cta & (CHUNKS - 1);
    const int base  = chunk * S;
    const int t     = threadIdx.x;
    const int lane  = t & 31;

    const float* __restrict__ xrow = x + (size_t)row * N0;

    // ---- Load owned span x_loc[8t..8t+7]; xv[i] = x_loc[8t-3+i] ----
    float xv[14];
    {
        const float4* __restrict__ xb =
            reinterpret_cast<const float4*>(xrow + base + 8 * t);
        float4 q0 = xb[0], q1 = xb[1];
        xv[3]  = q0.x; xv[4]  = q0.y; xv[5]  = q0.z; xv[6]  = q0.w;
        xv[7]  = q1.x; xv[8]  = q1.y; xv[9]  = q1.z; xv[10] = q1.w;
    }
    // Level-1 halo via shfl; warp-edge lanes load wrapped scalars.
    {
        float a = __shfl_up_sync(0xffffffffu, xv[8], 1);    // x[8t-3]
        float b = __shfl_up_sync(0xffffffffu, xv[9], 1);    // x[8t-2]
        float c = __shfl_up_sync(0xffffffffu, xv[10], 1);   // x[8t-1]
        if (lane == 0) {
            int g = base + 8 * t - 3;
            a = xrow[(g + N0)     & (N0 - 1)];
            b = xrow[(g + 1 + N0) & (N0 - 1)];
            c = xrow[(g + 2 + N0) & (N0 - 1)];
        }
        xv[0] = a; xv[1] = b; xv[2] = c;
        a = __shfl_down_sync(0xffffffffu, xv[3], 1);        // x[8t+8]
        b = __shfl_down_sync(0xffffffffu, xv[4], 1);        // x[8t+9]
        c = __shfl_down_sync(0xffffffffu, xv[5], 1);        // x[8t+10]
        if (lane == 31) {
            int g = base + 8 * t + 8;
            a = xrow[g & (N0 - 1)];
            b = xrow[(g + 1) & (N0 - 1)];
            c = xrow[(g + 2) & (N0 - 1)];
        }
        xv[11] = a; xv[12] = b; xv[13] = c;
    }

    // ---- Level 1: lo1[4t+k] = conv(xv+2k), hi1 stored as one float4 ----
    float lo1[4];
    {
        #pragma unroll
        for (int k = 0; k < 4; k++) lo1[k] = conv_lo(xv + 2 * k);

        float* __restrict__ hi1_out =
            out + OFF_HI1 + (size_t)row * (N0 / 2) + (size_t)chunk * (S / 2) + 4 * t;
        float4 hv = make_float4(conv_hi(xv + 0), conv_hi(xv + 2),
                                conv_hi(xv + 4), conv_hi(xv + 6));
        *reinterpret_cast<float4*>(hi1_out) = hv;

        eh1[t + 1] = make_float4(lo1[1], lo1[2], lo1[3], 0.0f);
        el1[t + 1] = make_float4(lo1[0], lo1[1], lo1[2], 0.0f);
    }

    // ---- Chunk-edge halo (threads 0 and 255), before first sync ----
    if (t == 0) {
        float hx[24];                         // hx[i] = x_loc[-21+i]
        #pragma unroll
        for (int i = 0; i < 21; i++)
            hx[i] = xrow[(base - 21 + i + N0) & (N0 - 1)];
        hx[21] = xv[3]; hx[22] = xv[4]; hx[23] = xv[5];       // x[0..2]
        float l1h[12];                        // l1h[i] = lo1[-9+i]
        #pragma unroll
        for (int u = 0; u < 9; u++) l1h[u] = conv_lo(hx + 2 * u);
        l1h[9] = lo1[0]; l1h[10] = lo1[1]; l1h[11] = lo1[2];
        eh1[0] = make_float4(l1h[6], l1h[7], l1h[8], 0.0f);   // lo1[-3..-1]
        lo2s[1] = conv_lo(l1h + 0);                           // lo2[-3]
        lo2s[2] = conv_lo(l1h + 2);                           // lo2[-2]
        lo2s[3] = conv_lo(l1h + 4);                           // lo2[-1]
    }
    if (t == THREADS - 1) {
        float hx[24];                         // hx[i] = x_loc[2045+i]
        hx[0] = xv[8]; hx[1] = xv[9]; hx[2] = xv[10];         // x[2045..2047]
        #pragma unroll
        for (int i = 3; i < 24; i++)
            hx[i] = xrow[(base + 2045 + i) & (N0 - 1)];       // x[2048..2068]
        float l1h[12];                        // l1h[i] = lo1[1021+i]
        l1h[0] = lo1[1]; l1h[1] = lo1[2]; l1h[2] = lo1[3];
        #pragma unroll
        for (int u = 0; u < 9; u++) l1h[3 + u] = conv_lo(hx + 2 * u);  // lo1[1024+u]
        el1[THREADS + 1] = make_float4(l1h[3], l1h[4], l1h[5], 0.0f);  // lo1[1024..1026]
        lo2s[516] = conv_lo(l1h + 0);                         // lo2[512]
        lo2s[517] = conv_lo(l1h + 2);                         // lo2[513]
        lo2s[518] = conv_lo(l1h + 4);                         // lo2[514]
    }
    __syncthreads();

    // ---- Level 2: lv[i] = lo1[4t-3+i], halo via shfl (edge lanes: smem) ----
    float lo2r[2];
    {
        float lv[10];
        lv[0] = __shfl_up_sync(0xffffffffu, lo1[1], 1);       // lo1[4t-3]
        lv[1] = __shfl_up_sync(0xffffffffu, lo1[2], 1);
        lv[2] = __shfl_up_sync(0xffffffffu, lo1[3], 1);
        lv[7] = __shfl_down_sync(0xffffffffu, lo1[0], 1);     // lo1[4t+4]
        lv[8] = __shfl_down_sync(0xffffffffu, lo1[1], 1);
        lv[9] = __shfl_down_sync(0xffffffffu, lo1[2], 1);
        if (lane == 0) {
            float4 hl = eh1[t];                               // lo1[4t-3..4t-1]
            lv[0] = hl.x; lv[1] = hl.y; lv[2] = hl.z;
        }
        if (lane == 31) {
            float4 lr = el1[t + 2];                           // lo1[4t+4..4t+6]
            lv[7] = lr.x; lv[8] = lr.y; lv[9] = lr.z;
        }
        lv[3] = lo1[0]; lv[4] = lo1[1]; lv[5] = lo1[2]; lv[6] = lo1[3];

        lo2r[0] = conv_lo(lv + 0);
        lo2r[1] = conv_lo(lv + 2);

        float* __restrict__ hi2_out =
            out + OFF_HI2 + (size_t)row * (N0 / 4) + (size_t)chunk * (S / 4) + 2 * t;
        float2 h2 = make_float2(conv_hi(lv + 0), conv_hi(lv + 2));
        *reinterpret_cast<float2*>(hi2_out) = h2;

        *reinterpret_cast<float2*>(&lo2s[4 + 2 * t]) = make_float2(lo2r[0], lo2r[1]);
    }
    __syncthreads();

    // ---- Level 3: mv[i] = lo2[2t-3+i]; outputs x0[t], hi3[t] ----
    {
        float mv[8];
        mv[0] = __shfl_up_sync(0xffffffffu, lo2r[1], 2);      // lo2[2t-3]
        mv[1] = __shfl_up_sync(0xffffffffu, lo2r[0], 1);      // lo2[2t-2]
        mv[2] = __shfl_up_sync(0xffffffffu, lo2r[1], 1);      // lo2[2t-1]
        mv[5] = __shfl_down_sync(0xffffffffu, lo2r[0], 1);    // lo2[2t+2]
        mv[6] = __shfl_down_sync(0xffffffffu, lo2r[1], 1);    // lo2[2t+3]
        mv[7] = __shfl_down_sync(0xffffffffu, lo2r[0], 2);    // lo2[2t+4]
        if (lane < 2) {
            mv[0] = lo2s[1 + 2 * t];                          // lo2[2t-3]
            mv[1] = lo2s[2 + 2 * t];
            mv[2] = lo2s[3 + 2 * t];
        }
        if (lane >= 30) {
            mv[5] = lo2s[6 + 2 * t];                          // lo2[2t+2]
            mv[6] = lo2s[7 + 2 * t];
            mv[7] = lo2s[8 + 2 * t];
        }
        mv[3] = lo2r[0]; mv[4] = lo2r[1];

        float* __restrict__ x0_out =
            out + (size_t)row * (N0 / 8) + (size_t)chunk * (S / 8) + t;
        float* __restrict__ hi3_out =
            out + OFF_HI3 + (size_t)row * (N0 / 8) + (size_t)chunk * (S / 8) + t;
        *x0_out  = conv_lo(mv);
        *hi3_out = conv_hi(mv);
    }
}

extern "C" void kernel_launch(void* const* d_in, const int* in_sizes, int n_in,
                              void* d_out, int out_size)
{
    const float* x = (const float*)d_in[0];
    float* out = (float*)d_out;
    dwt3_reg8_kernel<<<NROWS * CHUNKS, THREADS>>>(x, out);
}

// round 13
// speedup vs baseline: 1.0858x; 1.0858x over previous
#include <cuda_runtime.h>

// DWT1DForward (db4, periodic, J=3) — register cascade, 8 floats/thread,
// coalesced loads, uniform smem halo (flat lo1 + shifted-polyphase lo2).
// Thread t owns x[8t..8t+7] -> lo1/hi1[4t..4t+3] -> lo2/hi2[2t..2t+1] -> x0/hi3[t].
// d_out floats: [x0: 1024x8192][hi1: 1024x32768][hi2: 1024x16384][hi3: 1024x8192]

#define N0      65536
#define NROWS   1024
#define S       2048
#define CHUNKS  (N0 / S)          // 32
#define THREADS 256

#define OFF_HI1 8388608u
#define OFF_HI2 41943040u
#define OFF_HI3 58720256u

// db4 decomposition filters, REVERSED (as the reference passes them in).
#define H0_0 ( 0.23037781330885523f)
#define H0_1 ( 0.7148465705525415f)
#define H0_2 ( 0.6308807679295904f)
#define H0_3 (-0.02798376941698385f)
#define H0_4 (-0.18703481171888114f)
#define H0_5 ( 0.030841381835986965f)
#define H0_6 ( 0.032883011666982945f)
#define H0_7 (-0.010597401784997278f)

#define H1_0 (-0.010597401784997278f)
#define H1_1 (-0.032883011666982945f)
#define H1_2 ( 0.030841381835986965f)
#define H1_3 ( 0.18703481171888114f)
#define H1_4 (-0.02798376941698385f)
#define H1_5 (-0.6308807679295904f)
#define H1_6 ( 0.7148465705525415f)
#define H1_7 (-0.23037781330885523f)

// out[m] = sum_{i=0..7} H_i * x[2m-3+i]
__device__ __forceinline__ float conv_lo(const float* p) {
    return fmaf(p[0], H0_0, fmaf(p[1], H0_1, fmaf(p[2], H0_2, fmaf(p[3], H0_3,
           fmaf(p[4], H0_4, fmaf(p[5], H0_5, fmaf(p[6], H0_6, p[7] * H0_7)))))));
}
__device__ __forceinline__ float conv_hi(const float* p) {
    return fmaf(p[0], H1_0, fmaf(p[1], H1_1, fmaf(p[2], H1_2, fmaf(p[3], H1_3,
           fmaf(p[4], H1_4, fmaf(p[5], H1_5, fmaf(p[6], H1_6, p[7] * H1_7)))))));
}

__global__ __launch_bounds__(THREADS)
void dwt3_reg8u_kernel(const float* __restrict__ x, float* __restrict__ out)
{
    // Flat lo1 with halo: L[4+j] = lo1[j], j in [-3, 1028). Aligned for
    // float4 reads at L+4t-4+4 etc. (all byte offsets multiple of 16).
    __shared__ __align__(16) float L[1032];
    // Shifted polyphase lo2: Ps[i] = lo2[2i-3], Es[i] = lo2[2i-2], i in [0,259).
    __shared__ __align__(16) float Ps[260];
    __shared__ __align__(16) float Es[260];

    const int cta   = blockIdx.x;
    const int row   = cta >> 5;              // / CHUNKS
    const int chunk = cta & (CHUNKS - 1);
    const int base  = chunk * S;
    const int t     = threadIdx.x;
    const int lane  = t & 31;

    const float* __restrict__ xrow = x + (size_t)row * N0;

    // ---- Load owned span x[8t..8t+7]; xv[i] = x_loc[8t-3+i] ----
    float xv[14];
    {
        const float4* __restrict__ xb =
            reinterpret_cast<const float4*>(xrow + base + 8 * t);
        float4 q0 = xb[0], q1 = xb[1];
        xv[3]  = q0.x; xv[4]  = q0.y; xv[5]  = q0.z; xv[6]  = q0.w;
        xv[7]  = q1.x; xv[8]  = q1.y; xv[9]  = q1.z; xv[10] = q1.w;
    }
    // Level-1 halo via shfl; warp-edge lanes load wrapped scalars.
    {
        float a = __shfl_up_sync(0xffffffffu, xv[8], 1);    // x[8t-3]
        float b = __shfl_up_sync(0xffffffffu, xv[9], 1);    // x[8t-2]
        float c = __shfl_up_sync(0xffffffffu, xv[10], 1);   // x[8t-1]
        if (lane == 0) {
            int g = base + 8 * t - 3;
            a = xrow[(g + N0)     & (N0 - 1)];
            b = xrow[(g + 1 + N0) & (N0 - 1)];
            c = xrow[(g + 2 + N0) & (N0 - 1)];
        }
        xv[0] = a; xv[1] = b; xv[2] = c;
        a = __shfl_down_sync(0xffffffffu, xv[3], 1);        // x[8t+8]
        b = __shfl_down_sync(0xffffffffu, xv[4], 1);        // x[8t+9]
        c = __shfl_down_sync(0xffffffffu, xv[5], 1);        // x[8t+10]
        if (lane == 31) {
            int g = base + 8 * t + 8;
            a = xrow[g & (N0 - 1)];
            b = xrow[(g + 1) & (N0 - 1)];
            c = xrow[(g + 2) & (N0 - 1)];
        }
        xv[11] = a; xv[12] = b; xv[13] = c;
    }

    // ---- Level 1: lo1[4t+k] = conv(xv+2k); hi1 one coalesced STG.128 ----
    float lo1[4];
    {
        #pragma unroll
        for (int k = 0; k < 4; k++) lo1[k] = conv_lo(xv + 2 * k);

        float* __restrict__ hi1_out =
            out + OFF_HI1 + (size_t)row * (N0 / 2) + (size_t)chunk * (S / 2) + 4 * t;
        float4 hv = make_float4(conv_hi(xv + 0), conv_hi(xv + 2),
                                conv_hi(xv + 4), conv_hi(xv + 6));
        *reinterpret_cast<float4*>(hi1_out) = hv;

        *reinterpret_cast<float4*>(&L[4 + 4 * t]) =
            make_float4(lo1[0], lo1[1], lo1[2], lo1[3]);
    }

    // ---- Chunk-edge halo (threads 0 and 255), before first sync ----
    if (t == 0) {
        float hx[24];                         // hx[i] = x_loc[-21+i]
        #pragma unroll
        for (int i = 0; i < 21; i++)
            hx[i] = xrow[(base - 21 + i + N0) & (N0 - 1)];
        hx[21] = xv[3]; hx[22] = xv[4]; hx[23] = xv[5];       // x[0..2]
        float l1h[12];                        // l1h[i] = lo1[-9+i]
        #pragma unroll
        for (int u = 0; u < 9; u++) l1h[u] = conv_lo(hx + 2 * u);
        l1h[9] = lo1[0]; l1h[10] = lo1[1]; l1h[11] = lo1[2];
        L[1] = l1h[6]; L[2] = l1h[7]; L[3] = l1h[8];          // lo1[-3..-1]
        Ps[0] = conv_lo(l1h + 0);                             // lo2[-3]
        Es[0] = conv_lo(l1h + 2);                             // lo2[-2]
        Ps[1] = conv_lo(l1h + 4);                             // lo2[-1]
    }
    if (t == THREADS - 1) {
        float hx[24];                         // hx[i] = x_loc[2045+i]
        hx[0] = xv[8]; hx[1] = xv[9]; hx[2] = xv[10];         // x[2045..2047]
        #pragma unroll
        for (int i = 3; i < 24; i++)
            hx[i] = xrow[(base + 2045 + i) & (N0 - 1)];       // x[2048..2068]
        float l1h[12];                        // l1h[i] = lo1[1021+i]
        l1h[0] = lo1[1]; l1h[1] = lo1[2]; l1h[2] = lo1[3];
        #pragma unroll
        for (int u = 0; u < 9; u++) l1h[3 + u] = conv_lo(hx + 2 * u);  // lo1[1024+u]
        L[1028] = l1h[3]; L[1029] = l1h[4]; L[1030] = l1h[5]; // lo1[1024..1026]
        Es[257] = conv_lo(l1h + 0);                           // lo2[512]
        Ps[258] = conv_lo(l1h + 2);                           // lo2[513]
        Es[258] = conv_lo(l1h + 4);                           // lo2[514]
    }
    __syncthreads();

    // ---- Level 2: window lo1[4t-3..4t+6]; halo via 2 aligned LDS.128 ----
    {
        float4 hl = *reinterpret_cast<const float4*>(&L[4 * t]);       // lo1[4t-4..4t-1]
        float4 lr = *reinterpret_cast<const float4*>(&L[4 * t + 8]);   // lo1[4t+4..4t+7]
        float lv[10];
        lv[0] = hl.y; lv[1] = hl.z; lv[2] = hl.w;
        lv[3] = lo1[0]; lv[4] = lo1[1]; lv[5] = lo1[2]; lv[6] = lo1[3];
        lv[7] = lr.x; lv[8] = lr.y; lv[9] = lr.z;

        float lo2a = conv_lo(lv + 0);          // lo2[2t]
        float lo2b = conv_lo(lv + 2);          // lo2[2t+1]

        float* __restrict__ hi2_out =
            out + OFF_HI2 + (size_t)row * (N0 / 4) + (size_t)chunk * (S / 4) + 2 * t;
        *reinterpret_cast<float2*>(hi2_out) =
            make_float2(conv_hi(lv + 0), conv_hi(lv + 2));

        Es[t + 1] = lo2a;                      // lo2[2t]   = Es[t+1]
        Ps[t + 2] = lo2b;                      // lo2[2t+1] = Ps[t+2]
    }
    __syncthreads();

    // ---- Level 3: window lo2[2t-3..2t+4] via 2 aligned LDS.128 ----
    {
        float4 p4 = *reinterpret_cast<const float4*>(&Ps[4 * (t >> 2)] + (t & 3));
        float4 e4;
        // NOTE: Ps[t..t+3]/Es[t..t+3] are 16B-aligned only when t%4==0; use
        // element-exact aligned base: read as two overlapping aligned float4?
        // Simpler correct path: scalar-free aligned read via union when t%4==0
        // is not general -> fall back to safe unaligned-capable loads:
        p4 = make_float4(Ps[t], Ps[t + 1], Ps[t + 2], Ps[t + 3]);
        e4 = make_float4(Es[t], Es[t + 1], Es[t + 2], Es[t + 3]);
        float mv[8];
        mv[0] = p4.x; mv[1] = e4.x;            // lo2[2t-3], lo2[2t-2]
        mv[2] = p4.y; mv[3] = e4.y;            // lo2[2t-1], lo2[2t]
        mv[4] = p4.z; mv[5] = e4.z;            // lo2[2t+1], lo2[2t+2]
        mv[6] = p4.w; mv[7] = e4.w;            // lo2[2t+3], lo2[2t+4]

        float* __restrict__ x0_out =
            out + (size_t)row * (N0 / 8) + (size_t)chunk * (S / 8) + t;
        float* __restrict__ hi3_out =
            out + OFF_HI3 + (size_t)row * (N0 / 8) + (size_t)chunk * (S / 8) + t;
        *x0_out  = conv_lo(mv);
        *hi3_out = conv_hi(mv);
    }
}

extern "C" void kernel_launch(void* const* d_in, const int* in_sizes, int n_in,
                              void* d_out, int out_size)
{
    const float* x = (const float*)d_in[0];
    float* out = (float*)d_out;
    dwt3_reg8u_kernel<<<NROWS * CHUNKS, THREADS>>>(x, out);
}

// round 17
// speedup vs baseline: 1.2047x; 1.1096x over previous
#include <cuda_runtime.h>

// DWT1DForward (db4, periodic, J=3) — register cascade, 16 floats/thread,
// coalesced LDG via padded smem transpose, shfl/edge-slot halos (R8 base).
// Thread t owns x[16t..16t+15] -> lo1/hi1[8t..8t+7] -> lo2/hi2[4t..4t+3]
// -> x0/hi3[2t..2t+1].
// d_out floats: [x0: 1024x8192][hi1: 1024x32768][hi2: 1024x16384][hi3: 1024x8192]

#define N0      65536
#define NROWS   1024
#define S       2048
#define CHUNKS  (N0 / S)          // 32
#define THREADS 128

#define OFF_HI1 8388608u
#define OFF_HI2 41943040u
#define OFF_HI3 58720256u

// db4 decomposition filters, REVERSED (as the reference passes them in).
#define H0_0 ( 0.23037781330885523f)
#define H0_1 ( 0.7148465705525415f)
#define H0_2 ( 0.6308807679295904f)
#define H0_3 (-0.02798376941698385f)
#define H0_4 (-0.18703481171888114f)
#define H0_5 ( 0.030841381835986965f)
#define H0_6 ( 0.032883011666982945f)
#define H0_7 (-0.010597401784997278f)

#define H1_0 (-0.010597401784997278f)
#define H1_1 (-0.032883011666982945f)
#define H1_2 ( 0.030841381835986965f)
#define H1_3 ( 0.18703481171888114f)
#define H1_4 (-0.02798376941698385f)
#define H1_5 (-0.6308807679295904f)
#define H1_6 ( 0.7148465705525415f)
#define H1_7 (-0.23037781330885523f)

// out[m] = sum_{i=0..7} H_i * x[2m-3+i]
__device__ __forceinline__ float conv_lo(const float* p) {
    return fmaf(p[0], H0_0, fmaf(p[1], H0_1, fmaf(p[2], H0_2, fmaf(p[3], H0_3,
           fmaf(p[4], H0_4, fmaf(p[5], H0_5, fmaf(p[6], H0_6, p[7] * H0_7)))))));
}
__device__ __forceinline__ float conv_hi(const float* p) {
    return fmaf(p[0], H1_0, fmaf(p[1], H1_1, fmaf(p[2], H1_2, fmaf(p[3], H1_3,
           fmaf(p[4], H1_4, fmaf(p[5], H1_5, fmaf(p[6], H1_6, p[7] * H1_7)))))));
}

__global__ __launch_bounds__(THREADS)
void dwt3_regT_kernel(const float* __restrict__ x, float* __restrict__ out)
{
    // Edge-slot arrays: slot u (u in [-1,128]) at index u+1.
    __shared__ __align__(16) float4 eh1[THREADS + 2];
    __shared__ __align__(16) float4 el1[THREADS + 2];
    __shared__ __align__(16) float4 eh2[THREADS + 2];
    __shared__ __align__(16) float4 el2[THREADS + 2];
    // Transpose staging: per warp 128 float4 slots + 16B pad per 8 slots.
    // slot jj at float-idx 4*jj + 4*(jj>>3); 576 floats (2304B) per warp.
    __shared__ __align__(16) float xt[4 * 576];

    const int cta   = blockIdx.x;
    const int row   = cta >> 5;              // / CHUNKS
    const int chunk = cta & (CHUNKS - 1);
    const int base  = chunk * S;
    const int t     = threadIdx.x;
    const int lane  = t & 31;
    const int warp  = t >> 5;

    const float* __restrict__ xrow = x + (size_t)row * N0;

    // ---- Coalesced load of warp span, transpose through padded smem ----
    float xv[22];
    {
        const float4* __restrict__ xb4 =
            reinterpret_cast<const float4*>(xrow + base) + 128 * warp;
        float4 q0 = xb4[lane];
        float4 q1 = xb4[32 + lane];
        float4 q2 = xb4[64 + lane];
        float4 q3 = xb4[96 + lane];
        float* wb = xt + warp * 576;
        {
            int j0 = lane;       // slot jj = 32a + lane
            int j1 = 32 + lane;
            int j2 = 64 + lane;
            int j3 = 96 + lane;
            *reinterpret_cast<float4*>(wb + 4 * j0 + 4 * (j0 >> 3)) = q0;
            *reinterpret_cast<float4*>(wb + 4 * j1 + 4 * (j1 >> 3)) = q1;
            *reinterpret_cast<float4*>(wb + 4 * j2 + 4 * (j2 >> 3)) = q2;
            *reinterpret_cast<float4*>(wb + 4 * j3 + 4 * (j3 >> 3)) = q3;
        }
        __syncthreads();
        {
            int ib = 16 * lane + 4 * (lane >> 1);   // slots 4*lane..4*lane+3
            float4 p0 = *reinterpret_cast<const float4*>(wb + ib);
            float4 p1 = *reinterpret_cast<const float4*>(wb + ib + 4);
            float4 p2 = *reinterpret_cast<const float4*>(wb + ib + 8);
            float4 p3 = *reinterpret_cast<const float4*>(wb + ib + 12);
            xv[3]  = p0.x; xv[4]  = p0.y; xv[5]  = p0.z; xv[6]  = p0.w;
            xv[7]  = p1.x; xv[8]  = p1.y; xv[9]  = p1.z; xv[10] = p1.w;
            xv[11] = p2.x; xv[12] = p2.y; xv[13] = p2.z; xv[14] = p2.w;
            xv[15] = p3.x; xv[16] = p3.y; xv[17] = p3.z; xv[18] = p3.w;
        }
    }
    // Level-1 halo via shfl; warp-edge lanes load wrapped scalars.
    {
        float a = __shfl_up_sync(0xffffffffu, xv[16], 1);
        float b = __shfl_up_sync(0xffffffffu, xv[17], 1);
        float c = __shfl_up_sync(0xffffffffu, xv[18], 1);
        if (lane == 0) {
            int g = base + 16 * t - 3;
            a = xrow[(g + N0)     & (N0 - 1)];
            b = xrow[(g + 1 + N0) & (N0 - 1)];
            c = xrow[(g + 2 + N0) & (N0 - 1)];
        }
        xv[0] = a; xv[1] = b; xv[2] = c;
        a = __shfl_down_sync(0xffffffffu, xv[3], 1);
        b = __shfl_down_sync(0xffffffffu, xv[4], 1);
        c = __shfl_down_sync(0xffffffffu, xv[5], 1);
        if (lane == 31) {
            int g = base + 16 * t + 16;
            a = xrow[g & (N0 - 1)];
            b = xrow[(g + 1) & (N0 - 1)];
            c = xrow[(g + 2) & (N0 - 1)];
        }
        xv[19] = a; xv[20] = b; xv[21] = c;
    }

    // ---- Level 1: lo1[8t+k], hi1[8t+k], k=0..7; window xv[2k..2k+7] ----
    float lo1[8];
    {
        #pragma unroll
        for (int k = 0; k < 8; k++) lo1[k] = conv_lo(xv + 2 * k);

        float* __restrict__ hi1_out =
            out + OFF_HI1 + (size_t)row * (N0 / 2) + (size_t)chunk * (S / 2) + 8 * t;
        float4 h0 = make_float4(conv_hi(xv + 0), conv_hi(xv + 2),
                                conv_hi(xv + 4), conv_hi(xv + 6));
        float4 h1 = make_float4(conv_hi(xv + 8), conv_hi(xv + 10),
                                conv_hi(xv + 12), conv_hi(xv + 14));
        *reinterpret_cast<float4*>(hi1_out)     = h0;
        *reinterpret_cast<float4*>(hi1_out + 4) = h1;

        eh1[t + 1] = make_float4(lo1[5], lo1[6], lo1[7], 0.0f);
        el1[t + 1] = make_float4(lo1[0], lo1[1], lo1[2], 0.0f);
    }

    // ---- Chunk-edge halo slots (threads 0 and 127), before sync ----
    if (t == 0) {
        float hx[24];                         // hx[i] = x_loc[-21+i]
        #pragma unroll
        for (int i = 0; i < 21; i++)
            hx[i] = xrow[(base - 21 + i + N0) & (N0 - 1)];
        hx[21] = xv[3]; hx[22] = xv[4]; hx[23] = xv[5];   // x[0..2]
        float l1h[12];                        // l1h[i] = lo1[-9+i]
        #pragma unroll
        for (int u = 0; u < 9; u++) l1h[u] = conv_lo(hx + 2 * u);
        l1h[9] = lo1[0]; l1h[10] = lo1[1]; l1h[11] = lo1[2];
        eh1[0] = make_float4(l1h[6], l1h[7], l1h[8], 0.0f);   // lo1[-3..-1]
        eh2[0] = make_float4(conv_lo(l1h + 0), conv_lo(l1h + 2),
                             conv_lo(l1h + 4), 0.0f);         // lo2[-3..-1]
    }
    if (t == THREADS - 1) {
        float hx[24];                         // hx[i] = x_loc[2045+i]
        hx[0] = xv[16]; hx[1] = xv[17]; hx[2] = xv[18];       // x[2045..2047]
        #pragma unroll
        for (int i = 3; i < 24; i++)
            hx[i] = xrow[(base + 2045 + i) & (N0 - 1)];       // x[2048..2068]
        float l1h[12];                        // l1h[i] = lo1[1021+i]
        l1h[0] = lo1[5]; l1h[1] = lo1[6]; l1h[2] = lo1[7];
        #pragma unroll
        for (int u = 0; u < 9; u++) l1h[3 + u] = conv_lo(hx + 2 * u);  // lo1[1024+u]
        el1[THREADS + 1] = make_float4(l1h[3], l1h[4], l1h[5], 0.0f);  // lo1[1024..1026]
        el2[THREADS + 1] = make_float4(conv_lo(l1h + 0), conv_lo(l1h + 2),
                                       conv_lo(l1h + 4), 0.0f);        // lo2[512..514]
    }
    __syncthreads();

    // ---- Level 2: lv[i] = lo1[8t-3+i]; outputs 4t..4t+3 ----
    float lo2r[4];
    {
        float4 hl = eh1[t];                   // lo1[8t-3..8t-1]
        float4 lr = el1[t + 2];               // lo1[8t+8..8t+10]
        float lv[14];
        lv[0] = hl.x; lv[1] = hl.y; lv[2] = hl.z;
        #pragma unroll
        for (int k = 0; k < 8; k++) lv[3 + k] = lo1[k];
        lv[11] = lr.x; lv[12] = lr.y; lv[13] = lr.z;

        #pragma unroll
        for (int k = 0; k < 4; k++) lo2r[k] = conv_lo(lv + 2 * k);

        float* __restrict__ hi2_out =
            out + OFF_HI2 + (size_t)row * (N0 / 4) + (size_t)chunk * (S / 4) + 4 * t;
        float4 h2 = make_float4(conv_hi(lv + 0), conv_hi(lv + 2),
                                conv_hi(lv + 4), conv_hi(lv + 6));
        *reinterpret_cast<float4*>(hi2_out) = h2;

        eh2[t + 1] = make_float4(lo2r[1], lo2r[2], lo2r[3], 0.0f);
        el2[t + 1] = make_float4(lo2r[0], lo2r[1], lo2r[2], 0.0f);
    }
    __syncthreads();

    // ---- Level 3: mv[i] = lo2[4t-3+i]; outputs j = 2t, 2t+1 ----
    {
        float4 hl = eh2[t];                   // lo2[4t-3..4t-1]
        float4 lr = el2[t + 2];               // lo2[4t+4..4t+6]
        float mv[10];
        mv[0] = hl.x; mv[1] = hl.y; mv[2] = hl.z;
        mv[3] = lo2r[0]; mv[4] = lo2r[1]; mv[5] = lo2r[2]; mv[6] = lo2r[3];
        mv[7] = lr.x; mv[8] = lr.y; mv[9] = lr.z;

        float* __restrict__ x0_out =
            out + (size_t)row * (N0 / 8) + (size_t)chunk * (S / 8) + 2 * t;
        float* __restrict__ hi3_out =
            out + OFF_HI3 + (size_t)row * (N0 / 8) + (size_t)chunk * (S / 8) + 2 * t;
        float2 lv2 = make_float2(conv_lo(mv + 0), conv_lo(mv + 2));
        float2 hv2 = make_float2(conv_hi(mv + 0), conv_hi(mv + 2));
        *reinterpret_cast<float2*>(x0_out)  = lv2;
        *reinterpret_cast<float2*>(hi3_out) = hv2;
    }
}

extern "C" void kernel_launch(void* const* d_in, const int* in_sizes, int n_in,
                              void* d_out, int out_size)
{
    const float* x = (const float*)d_in[0];
    float* out = (float*)d_out;
    dwt3_regT_kernel<<<NROWS * CHUNKS, THREADS>>>(x, out);
}